// round 5
// baseline (speedup 1.0000x reference)
#include <cuda_runtime.h>
#include <cuda_bf16.h>

// ---------------------------------------------------------------------------
// PAConv fused pipeline v4: warp-owns-points GEMM (input re-read 8x -> 1x),
// channel-pair f32x2 accumulators, weights consumed as raw f32x2 from smem.
// Shapes: B=4, N=4096, K=32, Cin=Cout=64, m=8, P=B*N*K=524288, Q=B*N=16384.
// ---------------------------------------------------------------------------

#define Pn   524288
#define Qn   16384
#define NB   4096
#define EPS  1e-5f

typedef unsigned long long ull;

// ---- scratch -------------------------------------------------------------
__device__ float g_s0[64u * 524288u];     // layer0 raw   (134 MB)
__device__ float g_s1[32u * 524288u];     // layer1 raw   (67 MB)
__device__ float g_s2[16u * 524288u];     // layer2 raw   (33.5 MB)
__device__ float g_score[524288u * 8u];   // softmaxed scores [p][m]
__device__ float g_h[64u * 16384u];       // conv1 raw [c][q]
__device__ float g_y[16384u * 512u];      // y [q][m*64+o]
__device__ float g_outraw[4u * 64u * 4096u];
__device__ float g_stats[512];
__device__ float g_ab[512];
// stats/ab offsets:  bn1 0/64 | sn0 128/192 | sn1 256/288 | sn2 320/336 | bn2 352/416

// ---- f32x2 helpers -------------------------------------------------------
__device__ __forceinline__ ull dup2(float v) {
    ull r; asm("mov.b64 %0, {%1, %1};" : "=l"(r) : "f"(v)); return r;
}
__device__ __forceinline__ void fma2(ull& d, ull a, ull b) {
    asm("fma.rn.f32x2 %0, %1, %2, %0;" : "+l"(d) : "l"(a), "l"(b));
}
__device__ __forceinline__ float2 unpk(ull v) {
    float2 r; asm("mov.b64 {%0, %1}, %2;" : "=f"(r.x), "=f"(r.y) : "l"(v)); return r;
}

__global__ void zero_stats(float* st) {
    if (threadIdx.x < 512) st[threadIdx.x] = 0.f;
}

// ---------------------------------------------------------------------------
// GEMM v4: out[o*P + p] = sum_c W[o*C+c] * act(in(c,p))
// in(c,p) = in[b*BS + c*PB + (p - b*PB)], b = p0/PB (tile never crosses b).
// 256 threads; tile = 256*PL points. Warp owns 32*PL points; lane owns PL
// contiguous points and computes ALL O channels (channel-pair f32x2 accs).
// Weight pairs read via broadcast LDS.128 directly as f32x2 operands.
template<int C, int O, int PL, bool ACT>
__global__ __launch_bounds__(256, 2) void gemm3(
    const float* __restrict__ in, const float* __restrict__ W,
    const float* __restrict__ ab, float* __restrict__ out,
    int P, int PB, long BS)
{
    constexpr int PT = 256 * PL;
    extern __shared__ float sm[];
    float* Wt  = sm;              // [C][O]  (pair-contiguous channels)
    float* ins = sm + C * O;      // [C][PT]

    const int tid  = threadIdx.x;
    const int lane = tid & 31;
    const int wid  = tid >> 5;
    const int p0   = blockIdx.x * PT;
    const int b0   = p0 / PB;
    const long ibase = (long)b0 * BS + (long)(p0 - b0 * PB);

    for (int i = tid; i < C * O; i += 256) {
        int o = i / C, c = i - o * C;
        Wt[c * O + o] = W[i];
    }

    for (int i = tid; i < C * (PT / 4); i += 256) {
        int c  = i / (PT / 4);
        int p4 = (i - c * (PT / 4)) * 4;
        float4 v = *reinterpret_cast<const float4*>(in + ibase + (long)c * PB + p4);
        if (ACT) {
            float a = ab[c], b = ab[C + c];
            v.x = fmaxf(fmaf(a, v.x, b), 0.f);
            v.y = fmaxf(fmaf(a, v.y, b), 0.f);
            v.z = fmaxf(fmaf(a, v.z, b), 0.f);
            v.w = fmaxf(fmaf(a, v.w, b), 0.f);
        }
        *reinterpret_cast<float4*>(ins + c * PT + p4) = v;
    }
    __syncthreads();

    const int pt0 = wid * (32 * PL) + lane * PL;

    ull acc[O / 2][PL];
    #pragma unroll
    for (int j = 0; j < O / 2; j++)
        #pragma unroll
        for (int t = 0; t < PL; t++) acc[j][t] = 0ull;

    #pragma unroll 2
    for (int c = 0; c < C; c++) {
        const float* ic = ins + c * PT + pt0;
        ull in2[PL];
        #pragma unroll
        for (int t = 0; t < PL; t++) in2[t] = dup2(ic[t]);
        const ulonglong2* wp = reinterpret_cast<const ulonglong2*>(Wt + c * O);
        #pragma unroll
        for (int j2 = 0; j2 < O / 4; j2++) {
            ulonglong2 w = wp[j2];          // two channel-pairs, broadcast LDS.128
            #pragma unroll
            for (int t = 0; t < PL; t++) {
                fma2(acc[2 * j2][t],     w.x, in2[t]);
                fma2(acc[2 * j2 + 1][t], w.y, in2[t]);
            }
        }
    }

    const int p = p0 + pt0;
    if (PL == 1) {
        #pragma unroll
        for (int j = 0; j < O / 2; j++) {
            float2 f = unpk(acc[j][0]);
            out[(size_t)(2 * j)     * P + p] = f.x;
            out[(size_t)(2 * j + 1) * P + p] = f.y;
        }
    } else {
        #pragma unroll
        for (int j = 0; j < O / 2; j++) {
            float2 f0 = unpk(acc[j][0]);
            float2 f1 = unpk(acc[j][1]);
            *reinterpret_cast<float2*>(out + (size_t)(2 * j)     * P + p) = make_float2(f0.x, f1.x);
            *reinterpret_cast<float2*>(out + (size_t)(2 * j + 1) * P + p) = make_float2(f0.y, f1.y);
        }
    }
}

// ---------------------------------------------------------------------------
// per-channel sum / sumsq over channel-major buffer s[c*P + p]
__global__ __launch_bounds__(256) void stats_cp(
    const float* __restrict__ s, float* __restrict__ sum, float* __restrict__ sq,
    int P, int perblock)
{
    const int c = blockIdx.y;
    const size_t base = (size_t)c * P + (size_t)blockIdx.x * perblock;
    float ls = 0.f, lq = 0.f;
    for (int i = threadIdx.x * 4; i < perblock; i += 256 * 4) {
        float4 v = *reinterpret_cast<const float4*>(s + base + i);
        ls += (v.x + v.y) + (v.z + v.w);
        lq += v.x * v.x + v.y * v.y + v.z * v.z + v.w * v.w;
    }
    #pragma unroll
    for (int o = 16; o; o >>= 1) {
        ls += __shfl_xor_sync(0xffffffffu, ls, o);
        lq += __shfl_xor_sync(0xffffffffu, lq, o);
    }
    __shared__ float ws[8], wq[8];
    if ((threadIdx.x & 31) == 0) { ws[threadIdx.x >> 5] = ls; wq[threadIdx.x >> 5] = lq; }
    __syncthreads();
    if (threadIdx.x == 0) {
        float a = 0.f, b = 0.f;
        #pragma unroll
        for (int i = 0; i < 8; i++) { a += ws[i]; b += wq[i]; }
        atomicAdd(sum + c, a);
        atomicAdd(sq + c, b);
    }
}

// ---------------------------------------------------------------------------
__global__ void finalize_bn(
    const float* __restrict__ sum, const float* __restrict__ sq,
    const float* __restrict__ gam, const float* __restrict__ bet,
    float* __restrict__ ab, int C, float inv)
{
    int c = threadIdx.x;
    if (c < C) {
        float m   = sum[c] * inv;
        float var = sq[c] * inv - m * m;
        float s   = gam[c] * rsqrtf(var + EPS);
        ab[c]     = s;
        ab[C + c] = bet[c] - m * s;
    }
}

// ---------------------------------------------------------------------------
// y GEMM: y[q][k2] = sum_c relu(a1*h[c][q]+b1) * M2[c][k2]; 128q x 64k2 tile.
__global__ __launch_bounds__(256) void ygemm(
    const float* __restrict__ h, const float* __restrict__ M2,
    const float* __restrict__ ab, float* __restrict__ y)
{
    extern __shared__ float sm[];
    float* As = sm;               // [64][128]
    float* Bs = sm + 64 * 128;    // [64][64]

    const int tid = threadIdx.x;
    const int q0  = blockIdx.x * 128;
    const int k20 = blockIdx.y * 64;

    for (int i = tid; i < 64 * 128; i += 256) {
        int c = i >> 7, ql = i & 127;
        float v = h[c * Qn + q0 + ql];
        As[i] = fmaxf(fmaf(ab[c], v, ab[64 + c]), 0.f);
    }
    for (int i = tid; i < 64 * 64; i += 256) {
        int c = i >> 6, j = i & 63;
        Bs[i] = M2[c * 512 + k20 + j];
    }
    __syncthreads();

    const int kb = (tid & 7) * 8;
    const int qb = (tid >> 3) * 4;
    ull acc[2][8];
    #pragma unroll
    for (int t = 0; t < 2; t++)
        #pragma unroll
        for (int j = 0; j < 8; j++) acc[t][j] = 0ull;

    #pragma unroll 2
    for (int c = 0; c < 64; c++) {
        ulonglong2 ap = *reinterpret_cast<const ulonglong2*>(As + c * 128 + qb);
        ull av[2] = { ap.x, ap.y };
        ull bv[8];
        #pragma unroll
        for (int j = 0; j < 8; j++) bv[j] = dup2(Bs[c * 64 + kb + j]);
        #pragma unroll
        for (int t = 0; t < 2; t++)
            #pragma unroll
            for (int j = 0; j < 8; j++)
                fma2(acc[t][j], av[t], bv[j]);
    }

    #pragma unroll
    for (int t = 0; t < 2; t++) {
        float r0[8], r1[8];
        #pragma unroll
        for (int j = 0; j < 8; j++) {
            float2 f = unpk(acc[t][j]);
            r0[j] = f.x; r1[j] = f.y;
        }
        float* d0 = y + (size_t)(q0 + qb + 2 * t) * 512 + k20 + kb;
        float* d1 = d0 + 512;
        *reinterpret_cast<float4*>(d0)     = make_float4(r0[0], r0[1], r0[2], r0[3]);
        *reinterpret_cast<float4*>(d0 + 4) = make_float4(r0[4], r0[5], r0[6], r0[7]);
        *reinterpret_cast<float4*>(d1)     = make_float4(r1[0], r1[1], r1[2], r1[3]);
        *reinterpret_cast<float4*>(d1 + 4) = make_float4(r1[4], r1[5], r1[6], r1[7]);
    }
}

// ---------------------------------------------------------------------------
// ScoreNet layer3 (16 -> 8) + bias + softmax over m
__global__ __launch_bounds__(256) void l3_softmax(
    const float* __restrict__ s2, const float* __restrict__ w3,
    const float* __restrict__ bias3, const float* __restrict__ ab,
    float* __restrict__ score)
{
    __shared__ float W[128], B3[8], A2[16], B2[16];
    const int tid = threadIdx.x;
    if (tid < 128) W[tid] = w3[tid];
    if (tid < 8)   B3[tid] = bias3[tid];
    if (tid < 16)  { A2[tid] = ab[tid]; B2[tid] = ab[16 + tid]; }
    __syncthreads();

    const int p = blockIdx.x * 256 + tid;
    float v[16];
    #pragma unroll
    for (int c = 0; c < 16; c++) {
        float raw = s2[(size_t)c * Pn + p];
        v[c] = fmaxf(fmaf(A2[c], raw, B2[c]), 0.f);
    }
    float z[8];
    #pragma unroll
    for (int mi = 0; mi < 8; mi++) {
        float acc = B3[mi];
        #pragma unroll
        for (int c = 0; c < 16; c++) acc = fmaf(W[mi * 16 + c], v[c], acc);
        z[mi] = acc;
    }
    float mx = z[0];
    #pragma unroll
    for (int mi = 1; mi < 8; mi++) mx = fmaxf(mx, z[mi]);
    float se = 0.f;
    #pragma unroll
    for (int mi = 0; mi < 8; mi++) { z[mi] = __expf(z[mi] - mx); se += z[mi]; }
    float inv = 1.f / se;
    float* dst = score + (size_t)p * 8;
    *reinterpret_cast<float4*>(dst)     = make_float4(z[0]*inv, z[1]*inv, z[2]*inv, z[3]*inv);
    *reinterpret_cast<float4*>(dst + 4) = make_float4(z[4]*inv, z[5]*inv, z[6]*inv, z[7]*inv);
}

// ---------------------------------------------------------------------------
// gather + weighted sum + fused bn2 stats
__global__ __launch_bounds__(64) void gather_k(
    const float* __restrict__ y, const float* __restrict__ score,
    const int* __restrict__ idx, float* __restrict__ outr,
    float* __restrict__ sum, float* __restrict__ sq)
{
    __shared__ int id[32];
    __shared__ __align__(16) float sc[32][8];
    const int q   = blockIdx.x;
    const int tid = threadIdx.x;          // = o
    const int b   = q >> 12;
    const int n   = q & 4095;

    if (tid < 32) id[tid] = idx[(size_t)q * 32 + tid];
    reinterpret_cast<float4*>(sc)[tid] =
        reinterpret_cast<const float4*>(score + (size_t)q * 256)[tid];
    __syncthreads();

    float acc0 = 0.f, acc1 = 0.f;
    #pragma unroll 2
    for (int k = 0; k < 32; k++) {
        const float* yr = y + ((size_t)(b << 12) + id[k]) * 512 + tid;
        float4 sA = *reinterpret_cast<const float4*>(&sc[k][0]);
        float4 sB = *reinterpret_cast<const float4*>(&sc[k][4]);
        acc0 = fmaf(sA.x, yr[0 * 64], acc0);
        acc1 = fmaf(sA.y, yr[1 * 64], acc1);
        acc0 = fmaf(sA.z, yr[2 * 64], acc0);
        acc1 = fmaf(sA.w, yr[3 * 64], acc1);
        acc0 = fmaf(sB.x, yr[4 * 64], acc0);
        acc1 = fmaf(sB.y, yr[5 * 64], acc1);
        acc0 = fmaf(sB.z, yr[6 * 64], acc0);
        acc1 = fmaf(sB.w, yr[7 * 64], acc1);
    }
    float v = acc0 + acc1;
    outr[((size_t)(b * 64 + tid)) * NB + n] = v;
    atomicAdd(sum + tid, v);
    atomicAdd(sq  + tid, v * v);
}

__global__ __launch_bounds__(256) void apply_bn2(
    const float* __restrict__ outr, const float* __restrict__ ab,
    float* __restrict__ out)
{
    int i = blockIdx.x * 256 + threadIdx.x;
    int o = (i >> 12) & 63;
    out[i] = fmaxf(fmaf(ab[o], outr[i], ab[64 + o]), 0.f);
}

// ---------------------------------------------------------------------------
extern "C" void kernel_launch(void* const* d_in, const int* in_sizes, int n_in,
                              void* d_out, int out_size)
{
    const float* x     = (const float*)d_in[0];
    const float* xyz   = (const float*)d_in[1];
    const float* w1    = (const float*)d_in[2];
    const float* bn1g  = (const float*)d_in[3];
    const float* bn1b  = (const float*)d_in[4];
    const float* m2    = (const float*)d_in[5];
    const float* sw0   = (const float*)d_in[6];
    const float* sg0   = (const float*)d_in[7];
    const float* sb0   = (const float*)d_in[8];
    const float* sw1   = (const float*)d_in[9];
    const float* sg1   = (const float*)d_in[10];
    const float* sb1   = (const float*)d_in[11];
    const float* sw2   = (const float*)d_in[12];
    const float* sg2   = (const float*)d_in[13];
    const float* sb2   = (const float*)d_in[14];
    const float* sw3   = (const float*)d_in[15];
    const float* sbs3  = (const float*)d_in[16];
    const float* bn2g  = (const float*)d_in[17];
    const float* bn2b  = (const float*)d_in[18];
    const int*   idx   = (const int*)d_in[19];
    float* out = (float*)d_out;

    float *s0, *s1, *s2, *score, *h, *y, *outr, *st, *ab;
    cudaGetSymbolAddress((void**)&s0,    g_s0);
    cudaGetSymbolAddress((void**)&s1,    g_s1);
    cudaGetSymbolAddress((void**)&s2,    g_s2);
    cudaGetSymbolAddress((void**)&score, g_score);
    cudaGetSymbolAddress((void**)&h,     g_h);
    cudaGetSymbolAddress((void**)&y,     g_y);
    cudaGetSymbolAddress((void**)&outr,  g_outraw);
    cudaGetSymbolAddress((void**)&st,    g_stats);
    cudaGetSymbolAddress((void**)&ab,    g_ab);

    const int sm_l0 = (66*64 + 66*256) * 4;   // 84480
    const int sm_cv = (64*64 + 64*256) * 4;   // 81920
    const int sm_l1 = (64*32 + 64*256) * 4;   // 73728
    const int sm_l2 = (32*16 + 32*512) * 4;   // 67584
    const int sm_yg = (64*128 + 64*64) * 4;   // 49152
    cudaFuncSetAttribute((const void*)gemm3<66,64,1,false>, cudaFuncAttributeMaxDynamicSharedMemorySize, sm_l0);
    cudaFuncSetAttribute((const void*)gemm3<64,64,1,false>, cudaFuncAttributeMaxDynamicSharedMemorySize, sm_cv);
    cudaFuncSetAttribute((const void*)gemm3<64,32,1,true>,  cudaFuncAttributeMaxDynamicSharedMemorySize, sm_l1);
    cudaFuncSetAttribute((const void*)gemm3<32,16,2,true>,  cudaFuncAttributeMaxDynamicSharedMemorySize, sm_l2);
    cudaFuncSetAttribute((const void*)ygemm, cudaFuncAttributeMaxDynamicSharedMemorySize, sm_yg);

    const float invP = 1.f / (float)Pn;
    const float invQ = 1.f / (float)Qn;

    zero_stats<<<1, 512>>>(st);

    // ---- ScoreNet chain ----
    gemm3<66,64,1,false><<<Pn/256, 256, sm_l0>>>(
        xyz, sw0, nullptr, s0, Pn, 131072, 66L*131072);
    stats_cp<<<dim3(64, 64), 256>>>(s0, st + 128, st + 192, Pn, 8192);
    finalize_bn<<<1, 64>>>(st + 128, st + 192, sg0, sb0, ab + 128, 64, invP);

    gemm3<64,32,1,true><<<Pn/256, 256, sm_l1>>>(
        s0, sw1, ab + 128, s1, Pn, Pn, 0L);
    stats_cp<<<dim3(64, 32), 256>>>(s1, st + 256, st + 288, Pn, 8192);
    finalize_bn<<<1, 32>>>(st + 256, st + 288, sg1, sb1, ab + 256, 32, invP);

    gemm3<32,16,2,true><<<Pn/512, 256, sm_l2>>>(
        s1, sw2, ab + 256, s2, Pn, Pn, 0L);
    stats_cp<<<dim3(64, 16), 256>>>(s2, st + 320, st + 336, Pn, 8192);
    finalize_bn<<<1, 16>>>(st + 320, st + 336, sg2, sb2, ab + 320, 16, invP);

    l3_softmax<<<Pn/256, 256>>>(s2, sw3, sbs3, ab + 320, score);

    // ---- main path ----
    gemm3<64,64,1,false><<<Qn/256, 256, sm_cv>>>(
        x, w1, nullptr, h, Qn, 4096, 64L*4096);
    stats_cp<<<dim3(2, 64), 256>>>(h, st + 0, st + 64, Qn, 8192);
    finalize_bn<<<1, 64>>>(st + 0, st + 64, bn1g, bn1b, ab + 0, 64, invQ);

    ygemm<<<dim3(Qn/128, 8), 256, sm_yg>>>(h, m2, ab + 0, y);

    // ---- gather + bn2 ----
    gather_k<<<Qn, 64>>>(y, score, idx, outr, st + 352, st + 416);
    finalize_bn<<<1, 64>>>(st + 352, st + 416, bn2g, bn2b, ab + 352, 64, invQ);
    apply_bn2<<<4096, 256>>>(outr, ab + 352, out);
}

// round 6
// speedup vs baseline: 1.1883x; 1.1883x over previous
#include <cuda_runtime.h>
#include <cuda_bf16.h>

// ---------------------------------------------------------------------------
// PAConv v5: direct-LDG warp-owns-points GEMM (no input staging, no mainloop
// barriers), f32x2 FMA, finalize_bn folded into consumer prologues.
// Shapes: B=4, N=4096, K=32, Cin=Cout=64, m=8, P=B*N*K=524288, Q=B*N=16384.
// ---------------------------------------------------------------------------

#define Pn   524288
#define Qn   16384
#define NB   4096
#define EPS  1e-5f

typedef unsigned long long ull;

// ---- scratch -------------------------------------------------------------
__device__ float g_s0[64u * 524288u];
__device__ float g_s1[32u * 524288u];
__device__ float g_s2[16u * 524288u];
__device__ float g_score[524288u * 8u];
__device__ float g_h[64u * 16384u];
__device__ float g_y[16384u * 512u];
__device__ float g_outraw[4u * 64u * 4096u];
__device__ float g_stats[512];
// stats offsets: bn1 0/64 | sn0 128/192 | sn1 256/288 | sn2 320/336 | bn2 352/416

// ---- f32x2 helpers -------------------------------------------------------
__device__ __forceinline__ ull dup2(float v) {
    ull r; asm("mov.b64 %0, {%1, %1};" : "=l"(r) : "f"(v)); return r;
}
__device__ __forceinline__ void fma2(ull& d, ull a, ull b) {
    asm("fma.rn.f32x2 %0, %1, %2, %0;" : "+l"(d) : "l"(a), "l"(b));
}
__device__ __forceinline__ float2 unpk(ull v) {
    float2 r; asm("mov.b64 {%0, %1}, %2;" : "=f"(r.x), "=f"(r.y) : "l"(v)); return r;
}

__global__ void zero_stats(float* st) {
    if (threadIdx.x < 512) st[threadIdx.x] = 0.f;
}

// ---------------------------------------------------------------------------
// GEMM v5: out[o*P + p] = sum_c W[o*C+c] * act(in(c,p))
// in(c,p) = in[b*BS + c*PB + (p - b*PB)], b = p0/PB (tile never crosses b).
// 128 threads; block covers 128*PL points; warp w: [w*32*PL, +32PL),
// lane's points strided by 32 (coalesced LDG/STG). No input staging.
// ACT: affine (a,b) computed inline from (sum,sq,gam,bet) per block.
template<int C, int O, int PL, bool ACT>
__global__ __launch_bounds__(128, 4) void gemm4(
    const float* __restrict__ in, const float* __restrict__ W,
    const float* __restrict__ sum, const float* __restrict__ sq,
    const float* __restrict__ gam, const float* __restrict__ bet,
    float* __restrict__ out, int P, int PB, long BS, float inv)
{
    __shared__ __align__(16) float Wt[C * O];
    __shared__ float a_s[C], b_s[C];

    const int tid  = threadIdx.x;
    const int lane = tid & 31;
    const int wid  = tid >> 5;
    const int p0   = blockIdx.x * (128 * PL);
    const int b0   = p0 / PB;
    const long ibase = (long)b0 * BS + (long)(p0 - b0 * PB);

    for (int i = tid; i < C * O; i += 128) {
        int o = i / C, c = i - o * C;
        Wt[c * O + o] = W[i];
    }
    if (ACT) {
        if (tid < C) {
            float m   = sum[tid] * inv;
            float var = sq[tid] * inv - m * m;
            float s   = gam[tid] * rsqrtf(var + EPS);
            a_s[tid] = s;
            b_s[tid] = bet[tid] - m * s;
        }
    }
    __syncthreads();

    const int pw = wid * (32 * PL) + lane;       // + t*32 per t
    const float* ip = in + ibase + pw;

    ull acc[O / 2][PL];
    #pragma unroll
    for (int j = 0; j < O / 2; j++)
        #pragma unroll
        for (int t = 0; t < PL; t++) acc[j][t] = 0ull;

    constexpr int CH = (PL >= 4) ? 4 : ((C % 8 == 0) ? 8 : 6);
    static_assert(C % CH == 0, "chunk");

    for (int cc = 0; cc < C; cc += CH) {
        float v[CH][PL];
        #pragma unroll
        for (int u = 0; u < CH; u++)
            #pragma unroll
            for (int t = 0; t < PL; t++)
                v[u][t] = ip[(long)(cc + u) * PB + t * 32];
        if (ACT) {
            #pragma unroll
            for (int u = 0; u < CH; u++) {
                float a = a_s[cc + u], b = b_s[cc + u];
                #pragma unroll
                for (int t = 0; t < PL; t++)
                    v[u][t] = fmaxf(fmaf(a, v[u][t], b), 0.f);
            }
        }
        #pragma unroll
        for (int u = 0; u < CH; u++) {
            ull in2[PL];
            #pragma unroll
            for (int t = 0; t < PL; t++) in2[t] = dup2(v[u][t]);
            const ulonglong2* wp = reinterpret_cast<const ulonglong2*>(Wt + (cc + u) * O);
            #pragma unroll
            for (int j2 = 0; j2 < O / 4; j2++) {
                ulonglong2 w = wp[j2];       // broadcast LDS.128: 2 channel-pairs
                #pragma unroll
                for (int t = 0; t < PL; t++) {
                    fma2(acc[2 * j2][t],     w.x, in2[t]);
                    fma2(acc[2 * j2 + 1][t], w.y, in2[t]);
                }
            }
        }
    }

    #pragma unroll
    for (int j = 0; j < O / 2; j++)
        #pragma unroll
        for (int t = 0; t < PL; t++) {
            float2 f = unpk(acc[j][t]);
            out[(size_t)(2 * j)     * P + p0 + pw + t * 32] = f.x;
            out[(size_t)(2 * j + 1) * P + p0 + pw + t * 32] = f.y;
        }
}

// ---------------------------------------------------------------------------
// per-channel sum / sumsq over channel-major buffer s[c*P + p]
__global__ __launch_bounds__(256) void stats_cp(
    const float* __restrict__ s, float* __restrict__ sum, float* __restrict__ sq,
    int P, int perblock)
{
    const int c = blockIdx.y;
    const size_t base = (size_t)c * P + (size_t)blockIdx.x * perblock;
    float ls = 0.f, lq = 0.f;
    for (int i = threadIdx.x * 4; i < perblock; i += 256 * 4) {
        float4 v = *reinterpret_cast<const float4*>(s + base + i);
        ls += (v.x + v.y) + (v.z + v.w);
        lq += v.x * v.x + v.y * v.y + v.z * v.z + v.w * v.w;
    }
    #pragma unroll
    for (int o = 16; o; o >>= 1) {
        ls += __shfl_xor_sync(0xffffffffu, ls, o);
        lq += __shfl_xor_sync(0xffffffffu, lq, o);
    }
    __shared__ float ws[8], wq[8];
    if ((threadIdx.x & 31) == 0) { ws[threadIdx.x >> 5] = ls; wq[threadIdx.x >> 5] = lq; }
    __syncthreads();
    if (threadIdx.x == 0) {
        float a = 0.f, b = 0.f;
        #pragma unroll
        for (int i = 0; i < 8; i++) { a += ws[i]; b += wq[i]; }
        atomicAdd(sum + c, a);
        atomicAdd(sq + c, b);
    }
}

// ---------------------------------------------------------------------------
// y GEMM: y[q][k2] = sum_c relu(a1*h[c][q]+b1)*M2[c][k2]; bn1 finalize inline.
__global__ __launch_bounds__(256) void ygemm(
    const float* __restrict__ h, const float* __restrict__ M2,
    const float* __restrict__ sum, const float* __restrict__ sq,
    const float* __restrict__ gam, const float* __restrict__ bet,
    float* __restrict__ y, float inv)
{
    extern __shared__ float sm[];
    float* As  = sm;               // [64][128]
    float* Bs  = sm + 64 * 128;    // [64][64]
    float* a_s = Bs + 64 * 64;     // [64]
    float* b_s = a_s + 64;         // [64]

    const int tid = threadIdx.x;
    const int q0  = blockIdx.x * 128;
    const int k20 = blockIdx.y * 64;

    if (tid < 64) {
        float m   = sum[tid] * inv;
        float var = sq[tid] * inv - m * m;
        float s   = gam[tid] * rsqrtf(var + EPS);
        a_s[tid] = s;
        b_s[tid] = bet[tid] - m * s;
    }
    __syncthreads();

    for (int i = tid; i < 64 * 128; i += 256) {
        int c = i >> 7, ql = i & 127;
        float v = h[c * Qn + q0 + ql];
        As[i] = fmaxf(fmaf(a_s[c], v, b_s[c]), 0.f);
    }
    for (int i = tid; i < 64 * 64; i += 256) {
        int c = i >> 6, j = i & 63;
        Bs[i] = M2[c * 512 + k20 + j];
    }
    __syncthreads();

    const int kb = (tid & 7) * 8;
    const int qb = (tid >> 3) * 4;
    ull acc[2][8];
    #pragma unroll
    for (int t = 0; t < 2; t++)
        #pragma unroll
        for (int j = 0; j < 8; j++) acc[t][j] = 0ull;

    #pragma unroll 2
    for (int c = 0; c < 64; c++) {
        ulonglong2 ap = *reinterpret_cast<const ulonglong2*>(As + c * 128 + qb);
        ull av[2] = { ap.x, ap.y };
        ull bv[8];
        #pragma unroll
        for (int j = 0; j < 8; j++) bv[j] = dup2(Bs[c * 64 + kb + j]);
        #pragma unroll
        for (int t = 0; t < 2; t++)
            #pragma unroll
            for (int j = 0; j < 8; j++)
                fma2(acc[t][j], av[t], bv[j]);
    }

    #pragma unroll
    for (int t = 0; t < 2; t++) {
        float r0[8], r1[8];
        #pragma unroll
        for (int j = 0; j < 8; j++) {
            float2 f = unpk(acc[t][j]);
            r0[j] = f.x; r1[j] = f.y;
        }
        float* d0 = y + (size_t)(q0 + qb + 2 * t) * 512 + k20 + kb;
        float* d1 = d0 + 512;
        *reinterpret_cast<float4*>(d0)     = make_float4(r0[0], r0[1], r0[2], r0[3]);
        *reinterpret_cast<float4*>(d0 + 4) = make_float4(r0[4], r0[5], r0[6], r0[7]);
        *reinterpret_cast<float4*>(d1)     = make_float4(r1[0], r1[1], r1[2], r1[3]);
        *reinterpret_cast<float4*>(d1 + 4) = make_float4(r1[4], r1[5], r1[6], r1[7]);
    }
}

// ---------------------------------------------------------------------------
// ScoreNet layer3 (16 -> 8) + bias + softmax; sn2 finalize inline.
__global__ __launch_bounds__(256) void l3_softmax(
    const float* __restrict__ s2, const float* __restrict__ w3,
    const float* __restrict__ bias3,
    const float* __restrict__ sum, const float* __restrict__ sq,
    const float* __restrict__ gam, const float* __restrict__ bet,
    float* __restrict__ score, float inv)
{
    __shared__ float W[128], B3[8], A2[16], B2[16];
    const int tid = threadIdx.x;
    if (tid < 128) W[tid] = w3[tid];
    if (tid < 8)   B3[tid] = bias3[tid];
    if (tid < 16) {
        float m   = sum[tid] * inv;
        float var = sq[tid] * inv - m * m;
        float s   = gam[tid] * rsqrtf(var + EPS);
        A2[tid] = s;
        B2[tid] = bet[tid] - m * s;
    }
    __syncthreads();

    const int p = blockIdx.x * 256 + tid;
    float v[16];
    #pragma unroll
    for (int c = 0; c < 16; c++) {
        float raw = s2[(size_t)c * Pn + p];
        v[c] = fmaxf(fmaf(A2[c], raw, B2[c]), 0.f);
    }
    float z[8];
    #pragma unroll
    for (int mi = 0; mi < 8; mi++) {
        float acc = B3[mi];
        #pragma unroll
        for (int c = 0; c < 16; c++) acc = fmaf(W[mi * 16 + c], v[c], acc);
        z[mi] = acc;
    }
    float mx = z[0];
    #pragma unroll
    for (int mi = 1; mi < 8; mi++) mx = fmaxf(mx, z[mi]);
    float se = 0.f;
    #pragma unroll
    for (int mi = 0; mi < 8; mi++) { z[mi] = __expf(z[mi] - mx); se += z[mi]; }
    float is = 1.f / se;
    float* dst = score + (size_t)p * 8;
    *reinterpret_cast<float4*>(dst)     = make_float4(z[0]*is, z[1]*is, z[2]*is, z[3]*is);
    *reinterpret_cast<float4*>(dst + 4) = make_float4(z[4]*is, z[5]*is, z[6]*is, z[7]*is);
}

// ---------------------------------------------------------------------------
// gather + weighted sum + fused bn2 stats
__global__ __launch_bounds__(64) void gather_k(
    const float* __restrict__ y, const float* __restrict__ score,
    const int* __restrict__ idx, float* __restrict__ outr,
    float* __restrict__ sum, float* __restrict__ sq)
{
    __shared__ int id[32];
    __shared__ __align__(16) float sc[32][8];
    const int q   = blockIdx.x;
    const int tid = threadIdx.x;          // = o
    const int b   = q >> 12;
    const int n   = q & 4095;

    if (tid < 32) id[tid] = idx[(size_t)q * 32 + tid];
    reinterpret_cast<float4*>(sc)[tid] =
        reinterpret_cast<const float4*>(score + (size_t)q * 256)[tid];
    __syncthreads();

    float acc0 = 0.f, acc1 = 0.f;
    #pragma unroll 2
    for (int k = 0; k < 32; k++) {
        const float* yr = y + ((size_t)(b << 12) + id[k]) * 512 + tid;
        float4 sA = *reinterpret_cast<const float4*>(&sc[k][0]);
        float4 sB = *reinterpret_cast<const float4*>(&sc[k][4]);
        acc0 = fmaf(sA.x, yr[0 * 64], acc0);
        acc1 = fmaf(sA.y, yr[1 * 64], acc1);
        acc0 = fmaf(sA.z, yr[2 * 64], acc0);
        acc1 = fmaf(sA.w, yr[3 * 64], acc1);
        acc0 = fmaf(sB.x, yr[4 * 64], acc0);
        acc1 = fmaf(sB.y, yr[5 * 64], acc1);
        acc0 = fmaf(sB.z, yr[6 * 64], acc0);
        acc1 = fmaf(sB.w, yr[7 * 64], acc1);
    }
    float v = acc0 + acc1;
    outr[((size_t)(b * 64 + tid)) * NB + n] = v;
    atomicAdd(sum + tid, v);
    atomicAdd(sq  + tid, v * v);
}

// final bn2 + relu, finalize inline
__global__ __launch_bounds__(256) void apply_bn2(
    const float* __restrict__ outr,
    const float* __restrict__ sum, const float* __restrict__ sq,
    const float* __restrict__ gam, const float* __restrict__ bet,
    float* __restrict__ out, float inv)
{
    __shared__ float a_s[64], b_s[64];
    const int tid = threadIdx.x;
    if (tid < 64) {
        float m   = sum[tid] * inv;
        float var = sq[tid] * inv - m * m;
        float s   = gam[tid] * rsqrtf(var + EPS);
        a_s[tid] = s;
        b_s[tid] = bet[tid] - m * s;
    }
    __syncthreads();
    int i = blockIdx.x * 256 + tid;
    int o = (i >> 12) & 63;
    out[i] = fmaxf(fmaf(a_s[o], outr[i], b_s[o]), 0.f);
}

// ---------------------------------------------------------------------------
extern "C" void kernel_launch(void* const* d_in, const int* in_sizes, int n_in,
                              void* d_out, int out_size)
{
    const float* x     = (const float*)d_in[0];
    const float* xyz   = (const float*)d_in[1];
    const float* w1    = (const float*)d_in[2];
    const float* bn1g  = (const float*)d_in[3];
    const float* bn1b  = (const float*)d_in[4];
    const float* m2    = (const float*)d_in[5];
    const float* sw0   = (const float*)d_in[6];
    const float* sg0   = (const float*)d_in[7];
    const float* sb0   = (const float*)d_in[8];
    const float* sw1   = (const float*)d_in[9];
    const float* sg1   = (const float*)d_in[10];
    const float* sb1   = (const float*)d_in[11];
    const float* sw2   = (const float*)d_in[12];
    const float* sg2   = (const float*)d_in[13];
    const float* sb2   = (const float*)d_in[14];
    const float* sw3   = (const float*)d_in[15];
    const float* sbs3  = (const float*)d_in[16];
    const float* bn2g  = (const float*)d_in[17];
    const float* bn2b  = (const float*)d_in[18];
    const int*   idx   = (const int*)d_in[19];
    float* out = (float*)d_out;

    float *s0, *s1, *s2, *score, *h, *y, *outr, *st;
    cudaGetSymbolAddress((void**)&s0,    g_s0);
    cudaGetSymbolAddress((void**)&s1,    g_s1);
    cudaGetSymbolAddress((void**)&s2,    g_s2);
    cudaGetSymbolAddress((void**)&score, g_score);
    cudaGetSymbolAddress((void**)&h,     g_h);
    cudaGetSymbolAddress((void**)&y,     g_y);
    cudaGetSymbolAddress((void**)&outr,  g_outraw);
    cudaGetSymbolAddress((void**)&st,    g_stats);

    const int sm_yg = (64*128 + 64*64 + 128) * 4;   // 49664
    cudaFuncSetAttribute((const void*)ygemm, cudaFuncAttributeMaxDynamicSharedMemorySize, sm_yg);

    const float invP = 1.f / (float)Pn;
    const float invQ = 1.f / (float)Qn;

    zero_stats<<<1, 512>>>(st);

    // ---- ScoreNet chain ----
    gemm4<66,64,1,false><<<Pn/128, 128>>>(
        xyz, sw0, nullptr, nullptr, nullptr, nullptr, s0, Pn, 131072, 66L*131072, 0.f);
    stats_cp<<<dim3(64, 64), 256>>>(s0, st + 128, st + 192, Pn, 8192);

    gemm4<64,32,2,true><<<Pn/256, 128>>>(
        s0, sw1, st + 128, st + 192, sg0, sb0, s1, Pn, Pn, 0L, invP);
    stats_cp<<<dim3(64, 32), 256>>>(s1, st + 256, st + 288, Pn, 8192);

    gemm4<32,16,4,true><<<Pn/512, 128>>>(
        s1, sw2, st + 256, st + 288, sg1, sb1, s2, Pn, Pn, 0L, invP);
    stats_cp<<<dim3(64, 16), 256>>>(s2, st + 320, st + 336, Pn, 8192);

    l3_softmax<<<Pn/256, 256>>>(
        s2, sw3, sbs3, st + 320, st + 336, sg2, sb2, score, invP);

    // ---- main path ----
    gemm4<64,64,1,false><<<Qn/128, 128>>>(
        x, w1, nullptr, nullptr, nullptr, nullptr, h, Qn, 4096, 64L*4096, 0.f);
    stats_cp<<<dim3(2, 64), 256>>>(h, st + 0, st + 64, Qn, 8192);

    ygemm<<<dim3(Qn/128, 8), 256, sm_yg>>>(
        h, m2, st + 0, st + 64, bn1g, bn1b, y, invQ);

    // ---- gather + bn2 ----
    gather_k<<<Qn, 64>>>(y, score, idx, outr, st + 352, st + 416);
    apply_bn2<<<4096, 256>>>(outr, st + 352, st + 416, bn2g, bn2b, out, invQ);
}

// round 7
// speedup vs baseline: 1.2521x; 1.0537x over previous
#include <cuda_runtime.h>
#include <cuda_bf16.h>

// ---------------------------------------------------------------------------
// PAConv v6: GEMM weights in __constant__ (LDCU uniform path — off the L1
// crossbar), vectorized lane-contiguous input loads, no smem weight staging.
// Shapes: B=4, N=4096, K=32, Cin=Cout=64, m=8, P=B*N*K=524288, Q=B*N=16384.
// ---------------------------------------------------------------------------

#define Pn   524288
#define Qn   16384
#define NB   4096
#define EPS  1e-5f

typedef unsigned long long ull;

// ---- scratch -------------------------------------------------------------
__device__ float g_s0[64u * 524288u];
__device__ float g_s1[32u * 524288u];
__device__ float g_s2[16u * 524288u];
__device__ float g_score[524288u * 8u];
__device__ float g_h[64u * 16384u];
__device__ float g_y[16384u * 512u];
__device__ float g_outraw[4u * 64u * 4096u];
__device__ float g_stats[512];
__device__ float g_wt[10880];             // transposed weights staging
// stats offsets: bn1 0/64 | sn0 128/192 | sn1 256/288 | sn2 320/336 | bn2 352/416

// transposed weight bank: l0 @0 (66x64), conv1 @4224 (64x64),
// l1 @8320 (64x32), l2 @10368 (32x16); layout [c][O] pair-contiguous.
__constant__ float c_W[10880];
#define OFF_L0 0
#define OFF_CV 4224
#define OFF_L1 8320
#define OFF_L2 10368

// ---- f32x2 helpers -------------------------------------------------------
__device__ __forceinline__ ull dup2(float v) {
    ull r; asm("mov.b64 %0, {%1, %1};" : "=l"(r) : "f"(v)); return r;
}
__device__ __forceinline__ void fma2(ull& d, ull a, ull b) {
    asm("fma.rn.f32x2 %0, %1, %2, %0;" : "+l"(d) : "l"(a), "l"(b));
}
__device__ __forceinline__ float2 unpk(ull v) {
    float2 r; asm("mov.b64 {%0, %1}, %2;" : "=f"(r.x), "=f"(r.y) : "l"(v)); return r;
}

__global__ void zero_stats(float* st) {
    if (threadIdx.x < 512) st[threadIdx.x] = 0.f;
}

// transpose [O][C] -> [C][O] into the staging buffer (then D2D to c_W)
__global__ void transpose_w(
    const float* __restrict__ w0, const float* __restrict__ wc,
    const float* __restrict__ wl1, const float* __restrict__ wl2,
    float* __restrict__ dst)
{
    int t = blockIdx.x * 256 + threadIdx.x;
    if (t < 4224) {                       // l0: O=64, C=66
        int o = t / 66, c = t % 66;
        dst[OFF_L0 + c * 64 + o] = w0[t];
    } else if (t < 8320) {                // conv1: O=64, C=64
        int i = t - 4224, o = i >> 6, c = i & 63;
        dst[OFF_CV + c * 64 + o] = wc[i];
    } else if (t < 10368) {               // l1: O=32, C=64
        int i = t - 8320, o = i >> 6, c = i & 63;
        dst[OFF_L1 + c * 32 + o] = wl1[i];
    } else if (t < 10880) {               // l2: O=16, C=32
        int i = t - 10368, o = i >> 5, c = i & 31;
        dst[OFF_L2 + c * 16 + o] = wl2[i];
    }
}

// ---------------------------------------------------------------------------
// GEMM v6: out[o*P + p] = sum_c W[o,c] * act(in(c,p)), weights from c_W+woff.
// 128 threads; lane owns PL CONTIGUOUS points (vector LDG/STG); block covers
// 128*PL points. ACT: affine (a,b) computed inline from stats.
template<int C, int O, int PL, bool ACT>
__global__ __launch_bounds__(128, 4) void gemm5(
    const float* __restrict__ in, int woff,
    const float* __restrict__ sum, const float* __restrict__ sq,
    const float* __restrict__ gam, const float* __restrict__ bet,
    float* __restrict__ out, int P, int PB, long BS, float inv)
{
    __shared__ float a_s[C], b_s[C];

    const int tid  = threadIdx.x;
    const int lane = tid & 31;
    const int wid  = tid >> 5;
    const int p0   = blockIdx.x * (128 * PL);
    const int b0   = p0 / PB;
    const long ibase = (long)b0 * BS + (long)(p0 - b0 * PB);

    if (ACT) {
        if (tid < C) {
            float m   = sum[tid] * inv;
            float var = sq[tid] * inv - m * m;
            float s   = gam[tid] * rsqrtf(var + EPS);
            a_s[tid] = s;
            b_s[tid] = bet[tid] - m * s;
        }
        __syncthreads();
    }

    const int pw = (wid * 32 + lane) * PL;   // lane-contiguous PL points
    const float* ip = in + ibase + pw;

    ull acc[O / 2][PL];
    #pragma unroll
    for (int j = 0; j < O / 2; j++)
        #pragma unroll
        for (int t = 0; t < PL; t++) acc[j][t] = 0ull;

    constexpr int CH = (PL >= 4) ? 4 : ((C % 8 == 0) ? 8 : 6);
    static_assert(C % CH == 0, "chunk");

    for (int cc = 0; cc < C; cc += CH) {
        float v[CH][PL];
        #pragma unroll
        for (int u = 0; u < CH; u++) {
            const float* src = ip + (long)(cc + u) * PB;
            if (PL == 1) {
                v[u][0] = src[0];
            } else if (PL == 2) {
                float2 f = *reinterpret_cast<const float2*>(src);
                v[u][0] = f.x; v[u][1] = f.y;
            } else {
                float4 f = *reinterpret_cast<const float4*>(src);
                v[u][0] = f.x; v[u][1] = f.y; v[u][2] = f.z; v[u][3] = f.w;
            }
        }
        if (ACT) {
            #pragma unroll
            for (int u = 0; u < CH; u++) {
                float a = a_s[cc + u], b = b_s[cc + u];
                #pragma unroll
                for (int t = 0; t < PL; t++)
                    v[u][t] = fmaxf(fmaf(a, v[u][t], b), 0.f);
            }
        }
        #pragma unroll
        for (int u = 0; u < CH; u++) {
            ull in2[PL];
            #pragma unroll
            for (int t = 0; t < PL; t++) in2[t] = dup2(v[u][t]);
            const ull* wp = reinterpret_cast<const ull*>(c_W + woff + (cc + u) * O);
            #pragma unroll
            for (int j = 0; j < O / 2; j++) {
                ull w = wp[j];               // uniform const load (LDCU path)
                #pragma unroll
                for (int t = 0; t < PL; t++)
                    fma2(acc[j][t], w, in2[t]);
            }
        }
    }

    const int p = p0 + pw;
    #pragma unroll
    for (int j = 0; j < O / 2; j++) {
        if (PL == 1) {
            float2 f = unpk(acc[j][0]);
            out[(size_t)(2 * j)     * P + p] = f.x;
            out[(size_t)(2 * j + 1) * P + p] = f.y;
        } else if (PL == 2) {
            float2 f0 = unpk(acc[j][0]);
            float2 f1 = unpk(acc[j][1]);
            *reinterpret_cast<float2*>(out + (size_t)(2 * j)     * P + p) = make_float2(f0.x, f1.x);
            *reinterpret_cast<float2*>(out + (size_t)(2 * j + 1) * P + p) = make_float2(f0.y, f1.y);
        } else {
            float2 f0 = unpk(acc[j][0]);
            float2 f1 = unpk(acc[j][1]);
            float2 f2 = unpk(acc[j][2]);
            float2 f3 = unpk(acc[j][3]);
            *reinterpret_cast<float4*>(out + (size_t)(2 * j)     * P + p) = make_float4(f0.x, f1.x, f2.x, f3.x);
            *reinterpret_cast<float4*>(out + (size_t)(2 * j + 1) * P + p) = make_float4(f0.y, f1.y, f2.y, f3.y);
        }
    }
}

// ---------------------------------------------------------------------------
// per-channel sum / sumsq over channel-major buffer s[c*P + p]
__global__ __launch_bounds__(256) void stats_cp(
    const float* __restrict__ s, float* __restrict__ sum, float* __restrict__ sq,
    int P, int perblock)
{
    const int c = blockIdx.y;
    const size_t base = (size_t)c * P + (size_t)blockIdx.x * perblock;
    float ls = 0.f, lq = 0.f;
    for (int i = threadIdx.x * 4; i < perblock; i += 256 * 4) {
        float4 v = *reinterpret_cast<const float4*>(s + base + i);
        ls += (v.x + v.y) + (v.z + v.w);
        lq += v.x * v.x + v.y * v.y + v.z * v.z + v.w * v.w;
    }
    #pragma unroll
    for (int o = 16; o; o >>= 1) {
        ls += __shfl_xor_sync(0xffffffffu, ls, o);
        lq += __shfl_xor_sync(0xffffffffu, lq, o);
    }
    __shared__ float ws[8], wq[8];
    if ((threadIdx.x & 31) == 0) { ws[threadIdx.x >> 5] = ls; wq[threadIdx.x >> 5] = lq; }
    __syncthreads();
    if (threadIdx.x == 0) {
        float a = 0.f, b = 0.f;
        #pragma unroll
        for (int i = 0; i < 8; i++) { a += ws[i]; b += wq[i]; }
        atomicAdd(sum + c, a);
        atomicAdd(sq + c, b);
    }
}

// ---------------------------------------------------------------------------
// y GEMM: y[q][k2] = sum_c relu(a1*h[c][q]+b1)*M2[c][k2]; bn1 finalize inline.
__global__ __launch_bounds__(256) void ygemm(
    const float* __restrict__ h, const float* __restrict__ M2,
    const float* __restrict__ sum, const float* __restrict__ sq,
    const float* __restrict__ gam, const float* __restrict__ bet,
    float* __restrict__ y, float inv)
{
    extern __shared__ float sm[];
    float* As  = sm;               // [64][128]
    float* Bs  = sm + 64 * 128;    // [64][64]
    float* a_s = Bs + 64 * 64;     // [64]
    float* b_s = a_s + 64;         // [64]

    const int tid = threadIdx.x;
    const int q0  = blockIdx.x * 128;
    const int k20 = blockIdx.y * 64;

    if (tid < 64) {
        float m   = sum[tid] * inv;
        float var = sq[tid] * inv - m * m;
        float s   = gam[tid] * rsqrtf(var + EPS);
        a_s[tid] = s;
        b_s[tid] = bet[tid] - m * s;
    }
    __syncthreads();

    for (int i = tid; i < 64 * 128; i += 256) {
        int c = i >> 7, ql = i & 127;
        float v = h[c * Qn + q0 + ql];
        As[i] = fmaxf(fmaf(a_s[c], v, b_s[c]), 0.f);
    }
    for (int i = tid; i < 64 * 64; i += 256) {
        int c = i >> 6, j = i & 63;
        Bs[i] = M2[c * 512 + k20 + j];
    }
    __syncthreads();

    const int kb = (tid & 7) * 8;
    const int qb = (tid >> 3) * 4;
    ull acc[2][8];
    #pragma unroll
    for (int t = 0; t < 2; t++)
        #pragma unroll
        for (int j = 0; j < 8; j++) acc[t][j] = 0ull;

    #pragma unroll 2
    for (int c = 0; c < 64; c++) {
        ulonglong2 ap = *reinterpret_cast<const ulonglong2*>(As + c * 128 + qb);
        ull av[2] = { ap.x, ap.y };
        ull bv[8];
        #pragma unroll
        for (int j = 0; j < 8; j++) bv[j] = dup2(Bs[c * 64 + kb + j]);
        #pragma unroll
        for (int t = 0; t < 2; t++)
            #pragma unroll
            for (int j = 0; j < 8; j++)
                fma2(acc[t][j], av[t], bv[j]);
    }

    #pragma unroll
    for (int t = 0; t < 2; t++) {
        float r0[8], r1[8];
        #pragma unroll
        for (int j = 0; j < 8; j++) {
            float2 f = unpk(acc[t][j]);
            r0[j] = f.x; r1[j] = f.y;
        }
        float* d0 = y + (size_t)(q0 + qb + 2 * t) * 512 + k20 + kb;
        float* d1 = d0 + 512;
        *reinterpret_cast<float4*>(d0)     = make_float4(r0[0], r0[1], r0[2], r0[3]);
        *reinterpret_cast<float4*>(d0 + 4) = make_float4(r0[4], r0[5], r0[6], r0[7]);
        *reinterpret_cast<float4*>(d1)     = make_float4(r1[0], r1[1], r1[2], r1[3]);
        *reinterpret_cast<float4*>(d1 + 4) = make_float4(r1[4], r1[5], r1[6], r1[7]);
    }
}

// ---------------------------------------------------------------------------
// ScoreNet layer3 (16 -> 8) + bias + softmax; sn2 finalize inline.
__global__ __launch_bounds__(256) void l3_softmax(
    const float* __restrict__ s2, const float* __restrict__ w3,
    const float* __restrict__ bias3,
    const float* __restrict__ sum, const float* __restrict__ sq,
    const float* __restrict__ gam, const float* __restrict__ bet,
    float* __restrict__ score, float inv)
{
    __shared__ float W[128], B3[8], A2[16], B2[16];
    const int tid = threadIdx.x;
    if (tid < 128) W[tid] = w3[tid];
    if (tid < 8)   B3[tid] = bias3[tid];
    if (tid < 16) {
        float m   = sum[tid] * inv;
        float var = sq[tid] * inv - m * m;
        float s   = gam[tid] * rsqrtf(var + EPS);
        A2[tid] = s;
        B2[tid] = bet[tid] - m * s;
    }
    __syncthreads();

    const int p = blockIdx.x * 256 + tid;
    float v[16];
    #pragma unroll
    for (int c = 0; c < 16; c++) {
        float raw = s2[(size_t)c * Pn + p];
        v[c] = fmaxf(fmaf(A2[c], raw, B2[c]), 0.f);
    }
    float z[8];
    #pragma unroll
    for (int mi = 0; mi < 8; mi++) {
        float acc = B3[mi];
        #pragma unroll
        for (int c = 0; c < 16; c++) acc = fmaf(W[mi * 16 + c], v[c], acc);
        z[mi] = acc;
    }
    float mx = z[0];
    #pragma unroll
    for (int mi = 1; mi < 8; mi++) mx = fmaxf(mx, z[mi]);
    float se = 0.f;
    #pragma unroll
    for (int mi = 0; mi < 8; mi++) { z[mi] = __expf(z[mi] - mx); se += z[mi]; }
    float is = 1.f / se;
    float* dst = score + (size_t)p * 8;
    *reinterpret_cast<float4*>(dst)     = make_float4(z[0]*is, z[1]*is, z[2]*is, z[3]*is);
    *reinterpret_cast<float4*>(dst + 4) = make_float4(z[4]*is, z[5]*is, z[6]*is, z[7]*is);
}

// ---------------------------------------------------------------------------
// gather + weighted sum + fused bn2 stats
__global__ __launch_bounds__(64) void gather_k(
    const float* __restrict__ y, const float* __restrict__ score,
    const int* __restrict__ idx, float* __restrict__ outr,
    float* __restrict__ sum, float* __restrict__ sq)
{
    __shared__ int id[32];
    __shared__ __align__(16) float sc[32][8];
    const int q   = blockIdx.x;
    const int tid = threadIdx.x;          // = o
    const int b   = q >> 12;
    const int n   = q & 4095;

    if (tid < 32) id[tid] = idx[(size_t)q * 32 + tid];
    reinterpret_cast<float4*>(sc)[tid] =
        reinterpret_cast<const float4*>(score + (size_t)q * 256)[tid];
    __syncthreads();

    float acc0 = 0.f, acc1 = 0.f;
    #pragma unroll 2
    for (int k = 0; k < 32; k++) {
        const float* yr = y + ((size_t)(b << 12) + id[k]) * 512 + tid;
        float4 sA = *reinterpret_cast<const float4*>(&sc[k][0]);
        float4 sB = *reinterpret_cast<const float4*>(&sc[k][4]);
        acc0 = fmaf(sA.x, yr[0 * 64], acc0);
        acc1 = fmaf(sA.y, yr[1 * 64], acc1);
        acc0 = fmaf(sA.z, yr[2 * 64], acc0);
        acc1 = fmaf(sA.w, yr[3 * 64], acc1);
        acc0 = fmaf(sB.x, yr[4 * 64], acc0);
        acc1 = fmaf(sB.y, yr[5 * 64], acc1);
        acc0 = fmaf(sB.z, yr[6 * 64], acc0);
        acc1 = fmaf(sB.w, yr[7 * 64], acc1);
    }
    float v = acc0 + acc1;
    outr[((size_t)(b * 64 + tid)) * NB + n] = v;
    atomicAdd(sum + tid, v);
    atomicAdd(sq  + tid, v * v);
}

// final bn2 + relu, finalize inline
__global__ __launch_bounds__(256) void apply_bn2(
    const float* __restrict__ outr,
    const float* __restrict__ sum, const float* __restrict__ sq,
    const float* __restrict__ gam, const float* __restrict__ bet,
    float* __restrict__ out, float inv)
{
    __shared__ float a_s[64], b_s[64];
    const int tid = threadIdx.x;
    if (tid < 64) {
        float m   = sum[tid] * inv;
        float var = sq[tid] * inv - m * m;
        float s   = gam[tid] * rsqrtf(var + EPS);
        a_s[tid] = s;
        b_s[tid] = bet[tid] - m * s;
    }
    __syncthreads();
    int i = blockIdx.x * 256 + tid;
    int o = (i >> 12) & 63;
    out[i] = fmaxf(fmaf(a_s[o], outr[i], b_s[o]), 0.f);
}

// ---------------------------------------------------------------------------
extern "C" void kernel_launch(void* const* d_in, const int* in_sizes, int n_in,
                              void* d_out, int out_size)
{
    const float* x     = (const float*)d_in[0];
    const float* xyz   = (const float*)d_in[1];
    const float* w1    = (const float*)d_in[2];
    const float* bn1g  = (const float*)d_in[3];
    const float* bn1b  = (const float*)d_in[4];
    const float* m2    = (const float*)d_in[5];
    const float* sw0   = (const float*)d_in[6];
    const float* sg0   = (const float*)d_in[7];
    const float* sb0   = (const float*)d_in[8];
    const float* sw1   = (const float*)d_in[9];
    const float* sg1   = (const float*)d_in[10];
    const float* sb1   = (const float*)d_in[11];
    const float* sw2   = (const float*)d_in[12];
    const float* sg2   = (const float*)d_in[13];
    const float* sb2   = (const float*)d_in[14];
    const float* sw3   = (const float*)d_in[15];
    const float* sbs3  = (const float*)d_in[16];
    const float* bn2g  = (const float*)d_in[17];
    const float* bn2b  = (const float*)d_in[18];
    const int*   idx   = (const int*)d_in[19];
    float* out = (float*)d_out;

    float *s0, *s1, *s2, *score, *h, *y, *outr, *st, *wt;
    cudaGetSymbolAddress((void**)&s0,    g_s0);
    cudaGetSymbolAddress((void**)&s1,    g_s1);
    cudaGetSymbolAddress((void**)&s2,    g_s2);
    cudaGetSymbolAddress((void**)&score, g_score);
    cudaGetSymbolAddress((void**)&h,     g_h);
    cudaGetSymbolAddress((void**)&y,     g_y);
    cudaGetSymbolAddress((void**)&outr,  g_outraw);
    cudaGetSymbolAddress((void**)&st,    g_stats);
    cudaGetSymbolAddress((void**)&wt,    g_wt);

    const int sm_yg = (64*128 + 64*64 + 128) * 4;   // 49664
    cudaFuncSetAttribute((const void*)ygemm, cudaFuncAttributeMaxDynamicSharedMemorySize, sm_yg);

    const float invP = 1.f / (float)Pn;
    const float invQ = 1.f / (float)Qn;

    zero_stats<<<1, 512>>>(st);

    // transpose weights -> staging, then D2D into the constant bank
    transpose_w<<<43, 256>>>(sw0, w1, sw1, sw2, wt);
    cudaMemcpyToSymbolAsync(c_W, wt, 10880 * sizeof(float), 0,
                            cudaMemcpyDeviceToDevice);

    // ---- ScoreNet chain ----
    gemm5<66,64,1,false><<<Pn/128, 128>>>(
        xyz, OFF_L0, nullptr, nullptr, nullptr, nullptr, s0, Pn, 131072, 66L*131072, 0.f);
    stats_cp<<<dim3(64, 64), 256>>>(s0, st + 128, st + 192, Pn, 8192);

    gemm5<64,32,2,true><<<Pn/256, 128>>>(
        s0, OFF_L1, st + 128, st + 192, sg0, sb0, s1, Pn, Pn, 0L, invP);
    stats_cp<<<dim3(64, 32), 256>>>(s1, st + 256, st + 288, Pn, 8192);

    gemm5<32,16,4,true><<<Pn/512, 128>>>(
        s1, OFF_L2, st + 256, st + 288, sg1, sb1, s2, Pn, Pn, 0L, invP);
    stats_cp<<<dim3(64, 16), 256>>>(s2, st + 320, st + 336, Pn, 8192);

    l3_softmax<<<Pn/256, 256>>>(
        s2, sw3, sbs3, st + 320, st + 336, sg2, sb2, score, invP);

    // ---- main path ----
    gemm5<64,64,1,false><<<Qn/128, 128>>>(
        x, OFF_CV, nullptr, nullptr, nullptr, nullptr, h, Qn, 4096, 64L*4096, 0.f);
    stats_cp<<<dim3(2, 64), 256>>>(h, st + 0, st + 64, Qn, 8192);

    ygemm<<<dim3(Qn/128, 8), 256, sm_yg>>>(
        h, m2, st + 0, st + 64, bn1g, bn1b, y, invQ);

    // ---- gather + bn2 ----
    gather_k<<<Qn, 64>>>(y, score, idx, outr, st + 352, st + 416);
    apply_bn2<<<4096, 256>>>(outr, st + 352, st + 416, bn2g, bn2b, out, invQ);
}

// round 8
// speedup vs baseline: 1.3413x; 1.0712x over previous
#include <cuda_runtime.h>
#include <cuda_fp16.h>

// ---------------------------------------------------------------------------
// PAConv v7: LDCU.128 constant weights, fp16 ScoreNet scratch, f32x2 FMA.
// Shapes: B=4, N=4096, K=32, Cin=Cout=64, m=8, P=B*N*K=524288, Q=B*N=16384.
// ---------------------------------------------------------------------------

#define Pn   524288
#define Qn   16384
#define NB   4096
#define EPS  1e-5f

typedef unsigned long long ull;

// ---- scratch -------------------------------------------------------------
__device__ __half g_s0[64u * 524288u];    // 67 MB
__device__ __half g_s1[32u * 524288u];    // 33.5 MB
__device__ __half g_s2[16u * 524288u];    // 16.8 MB
__device__ float g_score[524288u * 8u];
__device__ float g_h[64u * 16384u];
__device__ float g_y[16384u * 512u];
__device__ float g_outraw[4u * 64u * 4096u];
__device__ float g_stats[512];
__device__ float g_wt[10880];
// stats offsets: bn1 0/64 | sn0 128/192 | sn1 256/288 | sn2 320/336 | bn2 352/416

__constant__ float c_W[10880];
#define OFF_L0 0
#define OFF_CV 4224
#define OFF_L1 8320
#define OFF_L2 10368

// ---- f32x2 helpers -------------------------------------------------------
__device__ __forceinline__ ull dup2(float v) {
    ull r; asm("mov.b64 %0, {%1, %1};" : "=l"(r) : "f"(v)); return r;
}
__device__ __forceinline__ void fma2(ull& d, ull a, ull b) {
    asm("fma.rn.f32x2 %0, %1, %2, %0;" : "+l"(d) : "l"(a), "l"(b));
}
__device__ __forceinline__ float2 unpk(ull v) {
    float2 r; asm("mov.b64 {%0, %1}, %2;" : "=f"(r.x), "=f"(r.y) : "l"(v)); return r;
}

__global__ void zero_stats(float* st) {
    if (threadIdx.x < 512) st[threadIdx.x] = 0.f;
}

// transpose [O][C] -> [C][O] into staging (then D2D to c_W)
__global__ void transpose_w(
    const float* __restrict__ w0, const float* __restrict__ wc,
    const float* __restrict__ wl1, const float* __restrict__ wl2,
    float* __restrict__ dst)
{
    int t = blockIdx.x * 256 + threadIdx.x;
    if (t < 4224) {
        int o = t / 66, c = t % 66;
        dst[OFF_L0 + c * 64 + o] = w0[t];
    } else if (t < 8320) {
        int i = t - 4224, o = i >> 6, c = i & 63;
        dst[OFF_CV + c * 64 + o] = wc[i];
    } else if (t < 10368) {
        int i = t - 8320, o = i >> 6, c = i & 63;
        dst[OFF_L1 + c * 32 + o] = wl1[i];
    } else if (t < 10880) {
        int i = t - 10368, o = i >> 5, c = i & 31;
        dst[OFF_L2 + c * 16 + o] = wl2[i];
    }
}

// ---------------------------------------------------------------------------
// GEMM: out[o*P + p] = sum_c W[o,c] * act(in(c,p)); weights via LDCU.128.
// 128 threads; lane owns PL contiguous points; block covers 128*PL points.
template<int C, int O, int PL, bool ACT, typename InT, typename OutT>
__global__ __launch_bounds__(128, 4) void gemm6(
    const InT* __restrict__ in, int woff,
    const float* __restrict__ sum, const float* __restrict__ sq,
    const float* __restrict__ gam, const float* __restrict__ bet,
    OutT* __restrict__ out, int P, int PB, long BS, float inv)
{
    __shared__ float a_s[C], b_s[C];

    const int tid  = threadIdx.x;
    const int lane = tid & 31;
    const int wid  = tid >> 5;
    const int p0   = blockIdx.x * (128 * PL);
    const int b0   = p0 / PB;
    const long ibase = (long)b0 * BS + (long)(p0 - b0 * PB);

    if (ACT) {
        if (tid < C) {
            float m   = sum[tid] * inv;
            float var = sq[tid] * inv - m * m;
            float s   = gam[tid] * rsqrtf(var + EPS);
            a_s[tid] = s;
            b_s[tid] = bet[tid] - m * s;
        }
        __syncthreads();
    }

    const int pw = (wid * 32 + lane) * PL;
    const InT* ip = in + ibase + pw;

    ull acc[O / 2][PL];
    #pragma unroll
    for (int j = 0; j < O / 2; j++)
        #pragma unroll
        for (int t = 0; t < PL; t++) acc[j][t] = 0ull;

    constexpr int CH = (PL >= 4) ? 4 : ((C % 8 == 0) ? 8 : 6);
    static_assert(C % CH == 0, "chunk");

    for (int cc = 0; cc < C; cc += CH) {
        float v[CH][PL];
        #pragma unroll
        for (int u = 0; u < CH; u++) {
            const InT* src = ip + (long)(cc + u) * PB;
            if constexpr (sizeof(InT) == 4) {
                if (PL == 1) {
                    v[u][0] = ((const float*)src)[0];
                } else if (PL == 2) {
                    float2 f = *reinterpret_cast<const float2*>(src);
                    v[u][0] = f.x; v[u][1] = f.y;
                } else {
                    float4 f = *reinterpret_cast<const float4*>(src);
                    v[u][0] = f.x; v[u][1] = f.y; v[u][2] = f.z; v[u][3] = f.w;
                }
            } else {
                if (PL == 1) {
                    v[u][0] = __half2float(*(const __half*)src);
                } else if (PL == 2) {
                    float2 f = __half22float2(*reinterpret_cast<const __half2*>(src));
                    v[u][0] = f.x; v[u][1] = f.y;
                } else {
                    uint2 r = *reinterpret_cast<const uint2*>(src);
                    float2 fa = __half22float2(*reinterpret_cast<__half2*>(&r.x));
                    float2 fb = __half22float2(*reinterpret_cast<__half2*>(&r.y));
                    v[u][0] = fa.x; v[u][1] = fa.y; v[u][2] = fb.x; v[u][3] = fb.y;
                }
            }
        }
        if (ACT) {
            #pragma unroll
            for (int u = 0; u < CH; u++) {
                float a = a_s[cc + u], b = b_s[cc + u];
                #pragma unroll
                for (int t = 0; t < PL; t++)
                    v[u][t] = fmaxf(fmaf(a, v[u][t], b), 0.f);
            }
        }
        #pragma unroll
        for (int u = 0; u < CH; u++) {
            ull in2[PL];
            #pragma unroll
            for (int t = 0; t < PL; t++) in2[t] = dup2(v[u][t]);
            const ulonglong2* wp =
                reinterpret_cast<const ulonglong2*>(c_W + woff + (cc + u) * O);
            #pragma unroll
            for (int j2 = 0; j2 < O / 4; j2++) {
                ulonglong2 w = wp[j2];       // LDCU.128: 2 channel-pairs
                #pragma unroll
                for (int t = 0; t < PL; t++) {
                    fma2(acc[2 * j2][t],     w.x, in2[t]);
                    fma2(acc[2 * j2 + 1][t], w.y, in2[t]);
                }
            }
        }
    }

    const int p = p0 + pw;
    #pragma unroll
    for (int j = 0; j < O / 2; j++) {
        if constexpr (sizeof(OutT) == 4) {
            float* o0 = (float*)out + (size_t)(2 * j) * P + p;
            float* o1 = (float*)out + (size_t)(2 * j + 1) * P + p;
            if (PL == 1) {
                float2 f = unpk(acc[j][0]);
                o0[0] = f.x; o1[0] = f.y;
            } else if (PL == 2) {
                float2 f0 = unpk(acc[j][0]), f1 = unpk(acc[j][1]);
                *reinterpret_cast<float2*>(o0) = make_float2(f0.x, f1.x);
                *reinterpret_cast<float2*>(o1) = make_float2(f0.y, f1.y);
            } else {
                float2 f0 = unpk(acc[j][0]), f1 = unpk(acc[j][1]);
                float2 f2 = unpk(acc[j][2]), f3 = unpk(acc[j][3]);
                *reinterpret_cast<float4*>(o0) = make_float4(f0.x, f1.x, f2.x, f3.x);
                *reinterpret_cast<float4*>(o1) = make_float4(f0.y, f1.y, f2.y, f3.y);
            }
        } else {
            __half* o0 = (__half*)out + (size_t)(2 * j) * P + p;
            __half* o1 = (__half*)out + (size_t)(2 * j + 1) * P + p;
            if (PL == 1) {
                float2 f = unpk(acc[j][0]);
                o0[0] = __float2half_rn(f.x);
                o1[0] = __float2half_rn(f.y);
            } else if (PL == 2) {
                float2 f0 = unpk(acc[j][0]), f1 = unpk(acc[j][1]);
                *reinterpret_cast<__half2*>(o0) = __floats2half2_rn(f0.x, f1.x);
                *reinterpret_cast<__half2*>(o1) = __floats2half2_rn(f0.y, f1.y);
            } else {
                float2 f0 = unpk(acc[j][0]), f1 = unpk(acc[j][1]);
                float2 f2 = unpk(acc[j][2]), f3 = unpk(acc[j][3]);
                __half2 h0a = __floats2half2_rn(f0.x, f1.x);
                __half2 h0b = __floats2half2_rn(f2.x, f3.x);
                __half2 h1a = __floats2half2_rn(f0.y, f1.y);
                __half2 h1b = __floats2half2_rn(f2.y, f3.y);
                uint2 u0, u1;
                u0.x = *reinterpret_cast<unsigned*>(&h0a);
                u0.y = *reinterpret_cast<unsigned*>(&h0b);
                u1.x = *reinterpret_cast<unsigned*>(&h1a);
                u1.y = *reinterpret_cast<unsigned*>(&h1b);
                *reinterpret_cast<uint2*>(o0) = u0;
                *reinterpret_cast<uint2*>(o1) = u1;
            }
        }
    }
}

// ---------------------------------------------------------------------------
// per-channel sum/sumsq, fp32 channel-major
__global__ __launch_bounds__(256) void stats_cp(
    const float* __restrict__ s, float* __restrict__ sum, float* __restrict__ sq,
    int P, int perblock)
{
    const int c = blockIdx.y;
    const size_t base = (size_t)c * P + (size_t)blockIdx.x * perblock;
    float ls = 0.f, lq = 0.f;
    for (int i = threadIdx.x * 4; i < perblock; i += 256 * 4) {
        float4 v = *reinterpret_cast<const float4*>(s + base + i);
        ls += (v.x + v.y) + (v.z + v.w);
        lq += v.x * v.x + v.y * v.y + v.z * v.z + v.w * v.w;
    }
    #pragma unroll
    for (int o = 16; o; o >>= 1) {
        ls += __shfl_xor_sync(0xffffffffu, ls, o);
        lq += __shfl_xor_sync(0xffffffffu, lq, o);
    }
    __shared__ float ws[8], wq[8];
    if ((threadIdx.x & 31) == 0) { ws[threadIdx.x >> 5] = ls; wq[threadIdx.x >> 5] = lq; }
    __syncthreads();
    if (threadIdx.x == 0) {
        float a = 0.f, b = 0.f;
        #pragma unroll
        for (int i = 0; i < 8; i++) { a += ws[i]; b += wq[i]; }
        atomicAdd(sum + c, a);
        atomicAdd(sq + c, b);
    }
}

// per-channel sum/sumsq, fp16 channel-major
__global__ __launch_bounds__(256) void stats_h(
    const __half* __restrict__ s, float* __restrict__ sum, float* __restrict__ sq,
    int P, int perblock)
{
    const int c = blockIdx.y;
    const size_t base = (size_t)c * P + (size_t)blockIdx.x * perblock;
    float ls = 0.f, lq = 0.f;
    for (int i = threadIdx.x * 8; i < perblock; i += 256 * 8) {
        uint4 r = *reinterpret_cast<const uint4*>(s + base + i);
        float2 f0 = __half22float2(*reinterpret_cast<__half2*>(&r.x));
        float2 f1 = __half22float2(*reinterpret_cast<__half2*>(&r.y));
        float2 f2 = __half22float2(*reinterpret_cast<__half2*>(&r.z));
        float2 f3 = __half22float2(*reinterpret_cast<__half2*>(&r.w));
        ls += (f0.x + f0.y) + (f1.x + f1.y) + (f2.x + f2.y) + (f3.x + f3.y);
        lq += f0.x*f0.x + f0.y*f0.y + f1.x*f1.x + f1.y*f1.y
            + f2.x*f2.x + f2.y*f2.y + f3.x*f3.x + f3.y*f3.y;
    }
    #pragma unroll
    for (int o = 16; o; o >>= 1) {
        ls += __shfl_xor_sync(0xffffffffu, ls, o);
        lq += __shfl_xor_sync(0xffffffffu, lq, o);
    }
    __shared__ float ws[8], wq[8];
    if ((threadIdx.x & 31) == 0) { ws[threadIdx.x >> 5] = ls; wq[threadIdx.x >> 5] = lq; }
    __syncthreads();
    if (threadIdx.x == 0) {
        float a = 0.f, b = 0.f;
        #pragma unroll
        for (int i = 0; i < 8; i++) { a += ws[i]; b += wq[i]; }
        atomicAdd(sum + c, a);
        atomicAdd(sq + c, b);
    }
}

// ---------------------------------------------------------------------------
// y GEMM: y[q][k2] = sum_c relu(a1*h[c][q]+b1)*M2[c][k2]; bn1 finalize inline.
__global__ __launch_bounds__(256) void ygemm(
    const float* __restrict__ h, const float* __restrict__ M2,
    const float* __restrict__ sum, const float* __restrict__ sq,
    const float* __restrict__ gam, const float* __restrict__ bet,
    float* __restrict__ y, float inv)
{
    extern __shared__ float sm[];
    float* As  = sm;
    float* Bs  = sm + 64 * 128;
    float* a_s = Bs + 64 * 64;
    float* b_s = a_s + 64;

    const int tid = threadIdx.x;
    const int q0  = blockIdx.x * 128;
    const int k20 = blockIdx.y * 64;

    if (tid < 64) {
        float m   = sum[tid] * inv;
        float var = sq[tid] * inv - m * m;
        float s   = gam[tid] * rsqrtf(var + EPS);
        a_s[tid] = s;
        b_s[tid] = bet[tid] - m * s;
    }
    __syncthreads();

    for (int i = tid; i < 64 * 128; i += 256) {
        int c = i >> 7, ql = i & 127;
        float v = h[c * Qn + q0 + ql];
        As[i] = fmaxf(fmaf(a_s[c], v, b_s[c]), 0.f);
    }
    for (int i = tid; i < 64 * 64; i += 256) {
        int c = i >> 6, j = i & 63;
        Bs[i] = M2[c * 512 + k20 + j];
    }
    __syncthreads();

    const int kb = (tid & 7) * 8;
    const int qb = (tid >> 3) * 4;
    ull acc[2][8];
    #pragma unroll
    for (int t = 0; t < 2; t++)
        #pragma unroll
        for (int j = 0; j < 8; j++) acc[t][j] = 0ull;

    #pragma unroll 2
    for (int c = 0; c < 64; c++) {
        ulonglong2 ap = *reinterpret_cast<const ulonglong2*>(As + c * 128 + qb);
        ull av[2] = { ap.x, ap.y };
        ull bv[8];
        #pragma unroll
        for (int j = 0; j < 8; j++) bv[j] = dup2(Bs[c * 64 + kb + j]);
        #pragma unroll
        for (int t = 0; t < 2; t++)
            #pragma unroll
            for (int j = 0; j < 8; j++)
                fma2(acc[t][j], av[t], bv[j]);
    }

    #pragma unroll
    for (int t = 0; t < 2; t++) {
        float r0[8], r1[8];
        #pragma unroll
        for (int j = 0; j < 8; j++) {
            float2 f = unpk(acc[t][j]);
            r0[j] = f.x; r1[j] = f.y;
        }
        float* d0 = y + (size_t)(q0 + qb + 2 * t) * 512 + k20 + kb;
        float* d1 = d0 + 512;
        *reinterpret_cast<float4*>(d0)     = make_float4(r0[0], r0[1], r0[2], r0[3]);
        *reinterpret_cast<float4*>(d0 + 4) = make_float4(r0[4], r0[5], r0[6], r0[7]);
        *reinterpret_cast<float4*>(d1)     = make_float4(r1[0], r1[1], r1[2], r1[3]);
        *reinterpret_cast<float4*>(d1 + 4) = make_float4(r1[4], r1[5], r1[6], r1[7]);
    }
}

// ---------------------------------------------------------------------------
// ScoreNet layer3 (16 -> 8, fp16 in) + bias + softmax; sn2 finalize inline.
__global__ __launch_bounds__(256) void l3_softmax(
    const __half* __restrict__ s2, const float* __restrict__ w3,
    const float* __restrict__ bias3,
    const float* __restrict__ sum, const float* __restrict__ sq,
    const float* __restrict__ gam, const float* __restrict__ bet,
    float* __restrict__ score, float inv)
{
    __shared__ float W[128], B3[8], A2[16], B2[16];
    const int tid = threadIdx.x;
    if (tid < 128) W[tid] = w3[tid];
    if (tid < 8)   B3[tid] = bias3[tid];
    if (tid < 16) {
        float m   = sum[tid] * inv;
        float var = sq[tid] * inv - m * m;
        float s   = gam[tid] * rsqrtf(var + EPS);
        A2[tid] = s;
        B2[tid] = bet[tid] - m * s;
    }
    __syncthreads();

    const int p = blockIdx.x * 256 + tid;
    float v[16];
    #pragma unroll
    for (int c = 0; c < 16; c++) {
        float raw = __half2float(s2[(size_t)c * Pn + p]);
        v[c] = fmaxf(fmaf(A2[c], raw, B2[c]), 0.f);
    }
    float z[8];
    #pragma unroll
    for (int mi = 0; mi < 8; mi++) {
        float acc = B3[mi];
        #pragma unroll
        for (int c = 0; c < 16; c++) acc = fmaf(W[mi * 16 + c], v[c], acc);
        z[mi] = acc;
    }
    float mx = z[0];
    #pragma unroll
    for (int mi = 1; mi < 8; mi++) mx = fmaxf(mx, z[mi]);
    float se = 0.f;
    #pragma unroll
    for (int mi = 0; mi < 8; mi++) { z[mi] = __expf(z[mi] - mx); se += z[mi]; }
    float is = 1.f / se;
    float* dst = score + (size_t)p * 8;
    *reinterpret_cast<float4*>(dst)     = make_float4(z[0]*is, z[1]*is, z[2]*is, z[3]*is);
    *reinterpret_cast<float4*>(dst + 4) = make_float4(z[4]*is, z[5]*is, z[6]*is, z[7]*is);
}

// ---------------------------------------------------------------------------
// gather + weighted sum + fused bn2 stats
__global__ __launch_bounds__(64) void gather_k(
    const float* __restrict__ y, const float* __restrict__ score,
    const int* __restrict__ idx, float* __restrict__ outr,
    float* __restrict__ sum, float* __restrict__ sq)
{
    __shared__ int id[32];
    __shared__ __align__(16) float sc[32][8];
    const int q   = blockIdx.x;
    const int tid = threadIdx.x;
    const int b   = q >> 12;
    const int n   = q & 4095;

    if (tid < 32) id[tid] = idx[(size_t)q * 32 + tid];
    reinterpret_cast<float4*>(sc)[tid] =
        reinterpret_cast<const float4*>(score + (size_t)q * 256)[tid];
    __syncthreads();

    float acc0 = 0.f, acc1 = 0.f;
    #pragma unroll 2
    for (int k = 0; k < 32; k++) {
        const float* yr = y + ((size_t)(b << 12) + id[k]) * 512 + tid;
        float4 sA = *reinterpret_cast<const float4*>(&sc[k][0]);
        float4 sB = *reinterpret_cast<const float4*>(&sc[k][4]);
        acc0 = fmaf(sA.x, yr[0 * 64], acc0);
        acc1 = fmaf(sA.y, yr[1 * 64], acc1);
        acc0 = fmaf(sA.z, yr[2 * 64], acc0);
        acc1 = fmaf(sA.w, yr[3 * 64], acc1);
        acc0 = fmaf(sB.x, yr[4 * 64], acc0);
        acc1 = fmaf(sB.y, yr[5 * 64], acc1);
        acc0 = fmaf(sB.z, yr[6 * 64], acc0);
        acc1 = fmaf(sB.w, yr[7 * 64], acc1);
    }
    float v = acc0 + acc1;
    outr[((size_t)(b * 64 + tid)) * NB + n] = v;
    atomicAdd(sum + tid, v);
    atomicAdd(sq  + tid, v * v);
}

// final bn2 + relu, finalize inline
__global__ __launch_bounds__(256) void apply_bn2(
    const float* __restrict__ outr,
    const float* __restrict__ sum, const float* __restrict__ sq,
    const float* __restrict__ gam, const float* __restrict__ bet,
    float* __restrict__ out, float inv)
{
    __shared__ float a_s[64], b_s[64];
    const int tid = threadIdx.x;
    if (tid < 64) {
        float m   = sum[tid] * inv;
        float var = sq[tid] * inv - m * m;
        float s   = gam[tid] * rsqrtf(var + EPS);
        a_s[tid] = s;
        b_s[tid] = bet[tid] - m * s;
    }
    __syncthreads();
    int i = blockIdx.x * 256 + tid;
    int o = (i >> 12) & 63;
    out[i] = fmaxf(fmaf(a_s[o], outr[i], b_s[o]), 0.f);
}

// ---------------------------------------------------------------------------
extern "C" void kernel_launch(void* const* d_in, const int* in_sizes, int n_in,
                              void* d_out, int out_size)
{
    const float* x     = (const float*)d_in[0];
    const float* xyz   = (const float*)d_in[1];
    const float* w1    = (const float*)d_in[2];
    const float* bn1g  = (const float*)d_in[3];
    const float* bn1b  = (const float*)d_in[4];
    const float* m2    = (const float*)d_in[5];
    const float* sw0   = (const float*)d_in[6];
    const float* sg0   = (const float*)d_in[7];
    const float* sb0   = (const float*)d_in[8];
    const float* sw1   = (const float*)d_in[9];
    const float* sg1   = (const float*)d_in[10];
    const float* sb1   = (const float*)d_in[11];
    const float* sw2   = (const float*)d_in[12];
    const float* sg2   = (const float*)d_in[13];
    const float* sb2   = (const float*)d_in[14];
    const float* sw3   = (const float*)d_in[15];
    const float* sbs3  = (const float*)d_in[16];
    const float* bn2g  = (const float*)d_in[17];
    const float* bn2b  = (const float*)d_in[18];
    const int*   idx   = (const int*)d_in[19];
    float* out = (float*)d_out;

    __half *s0, *s1, *s2;
    float *score, *h, *y, *outr, *st, *wt;
    cudaGetSymbolAddress((void**)&s0,    g_s0);
    cudaGetSymbolAddress((void**)&s1,    g_s1);
    cudaGetSymbolAddress((void**)&s2,    g_s2);
    cudaGetSymbolAddress((void**)&score, g_score);
    cudaGetSymbolAddress((void**)&h,     g_h);
    cudaGetSymbolAddress((void**)&y,     g_y);
    cudaGetSymbolAddress((void**)&outr,  g_outraw);
    cudaGetSymbolAddress((void**)&st,    g_stats);
    cudaGetSymbolAddress((void**)&wt,    g_wt);

    const int sm_yg = (64*128 + 64*64 + 128) * 4;   // 49664
    cudaFuncSetAttribute((const void*)ygemm, cudaFuncAttributeMaxDynamicSharedMemorySize, sm_yg);

    const float invP = 1.f / (float)Pn;
    const float invQ = 1.f / (float)Qn;

    zero_stats<<<1, 512>>>(st);

    transpose_w<<<43, 256>>>(sw0, w1, sw1, sw2, wt);
    cudaMemcpyToSymbolAsync(c_W, wt, 10880 * sizeof(float), 0,
                            cudaMemcpyDeviceToDevice);

    // ---- ScoreNet chain ----
    gemm6<66,64,1,false,float,__half><<<Pn/128, 128>>>(
        xyz, OFF_L0, nullptr, nullptr, nullptr, nullptr, s0, Pn, 131072, 66L*131072, 0.f);
    stats_h<<<dim3(64, 64), 256>>>(s0, st + 128, st + 192, Pn, 8192);

    gemm6<64,32,2,true,__half,__half><<<Pn/256, 128>>>(
        s0, OFF_L1, st + 128, st + 192, sg0, sb0, s1, Pn, Pn, 0L, invP);
    stats_h<<<dim3(64, 32), 256>>>(s1, st + 256, st + 288, Pn, 8192);

    gemm6<32,16,4,true,__half,__half><<<Pn/512, 128>>>(
        s1, OFF_L2, st + 256, st + 288, sg1, sb1, s2, Pn, Pn, 0L, invP);
    stats_h<<<dim3(64, 16), 256>>>(s2, st + 320, st + 336, Pn, 8192);

    l3_softmax<<<Pn/256, 256>>>(
        s2, sw3, sbs3, st + 320, st + 336, sg2, sb2, score, invP);

    // ---- main path ----
    gemm6<64,64,1,false,float,float><<<Qn/128, 128>>>(
        x, OFF_CV, nullptr, nullptr, nullptr, nullptr, h, Qn, 4096, 64L*4096, 0.f);
    stats_cp<<<dim3(2, 64), 256>>>(h, st + 0, st + 64, Qn, 8192);

    ygemm<<<dim3(Qn/128, 8), 256, sm_yg>>>(
        h, m2, st + 0, st + 64, bn1g, bn1b, y, invQ);

    // ---- gather + bn2 ----
    gather_k<<<Qn, 64>>>(y, score, idx, outr, st + 352, st + 416);
    apply_bn2<<<4096, 256>>>(outr, st + 352, st + 416, bn2g, bn2b, out, invQ);
}